// round 2
// baseline (speedup 1.0000x reference)
#include <cuda_runtime.h>
#include <math.h>

// Problem constants (fixed by the reference setup_inputs)
#define BB 16      // batch (both sides)
#define SS 512     // sequence length
#define HH 128     // hidden
#define TT 32      // band half-width: w(delta>32) <= 6.9e-8 -> linearized exactly enough
#define SC 64      // s-chunk per block in main kernel
#define TW 128     // t-window per block = SC + 2*TT
#define NC (SS/SC) // 8 chunks

// ---------------- device scratch (no allocations allowed) ----------------
__device__ float g_qn[BB*SS*HH];     // normalized queries
__device__ float g_kn[BB*SS*HH];     // normalized keys
__device__ float g_ksum[BB*HH];      // per-j masked sum of normalized keys
__device__ float g_kcnt[BB];         // per-j count of valid keys
__device__ float g_qdenom[BB];       // per-i max(sum(q_mask),1)
__device__ float g_S1[BB*BB*SS];     // S1[i][j][s] = qhat_s . ksum_j
__device__ float g_partial[BB*BB*NC];
__device__ float g_wtab[TT+1];       // exp(-0.5*delta)

// ---------------- packed f32x2 helpers (sm_100a) ----------------
#define FFMA2(d,a,b) asm("fma.rn.f32x2 %0, %1, %2, %0;" : "+l"(d) : "l"(a), "l"(b))
#define PACK2(d,x)   asm("mov.b64 %0, {%1, %1};" : "=l"(d) : "r"(__float_as_uint(x)))
#define UNPACK2(lo,hi,d) do { unsigned int _u0,_u1; \
    asm("mov.b64 {%0, %1}, %2;" : "=r"(_u0), "=r"(_u1) : "l"(d)); \
    lo = __uint_as_float(_u0); hi = __uint_as_float(_u1); } while(0)

// ---------------- K1: L2-normalize q and k rows ----------------
__global__ void k_norm(const float* __restrict__ qe, const float* __restrict__ ke) {
    int row  = blockIdx.x * 8 + (threadIdx.x >> 5);   // 8 warps per block, 1 row/warp
    int lane = threadIdx.x & 31;
    const float* src; float* dst;
    if (row < BB*SS) { src = qe + (size_t)row*HH; dst = g_qn + (size_t)row*HH; }
    else             { int r = row - BB*SS; src = ke + (size_t)r*HH; dst = g_kn + (size_t)r*HH; }
    float4 v = reinterpret_cast<const float4*>(src)[lane];
    float ss = v.x*v.x + v.y*v.y + v.z*v.z + v.w*v.w;
    #pragma unroll
    for (int off = 16; off >= 1; off >>= 1) ss += __shfl_xor_sync(0xffffffffu, ss, off);
    float sc = 1.0f / fmaxf(sqrtf(ss), 1e-12f);
    v.x *= sc; v.y *= sc; v.z *= sc; v.w *= sc;
    reinterpret_cast<float4*>(dst)[lane] = v;
}

// ---------------- K2: per-j masked key sums, counts, denoms, w-table ----------------
__global__ void k_prep(const float* __restrict__ km, const float* __restrict__ qm) {
    __shared__ float kms[SS];
    __shared__ float qmsm[SS];
    int j = blockIdx.x, tid = threadIdx.x;   // 128 threads
    for (int t = tid; t < SS; t += 128) {
        // binary-gate key mask (matches exp(-(1-v)*1e9)=0 for any v<1)
        kms[t]  = (km[j*SS + t] > 0.999f) ? 1.0f : 0.0f;
        qmsm[t] = qm[j*SS + t];
    }
    __syncthreads();
    float acc = 0.0f;
    #pragma unroll 4
    for (int t = 0; t < SS; t++) acc += g_kn[((size_t)j*SS + t)*HH + tid] * kms[t];
    g_ksum[j*HH + tid] = acc;
    if (tid == 0) {
        float a = 0.f, b = 0.f;
        for (int t = 0; t < SS; t++) { a += kms[t]; b += qmsm[t]; }
        g_kcnt[j] = a;
        g_qdenom[j] = fmaxf(b, 1.0f);
    }
    if (blockIdx.x == 0 && tid <= TT) g_wtab[tid] = expf(-0.5f * (float)tid);
}

// ---------------- K3: S1[i][j][s] = qhat_s . ksum_j ----------------
__global__ void k_s1() {
    __shared__ float ks[BB*HH];
    int tid = threadIdx.x;
    for (int x = tid; x < BB*HH; x += 256) ks[x] = g_ksum[x];
    __syncthreads();
    int w = tid >> 5, lane = tid & 31;
    int row = blockIdx.x * 8 + w;            // 0..8191
    int i = row >> 9, s = row & (SS-1);
    float4 q = *reinterpret_cast<const float4*>(&g_qn[(size_t)row*HH + lane*4]);
    #pragma unroll
    for (int j = 0; j < BB; j++) {
        float4 k4 = *reinterpret_cast<const float4*>(&ks[j*HH + lane*4]);
        float p = q.x*k4.x + q.y*k4.y + q.z*k4.z + q.w*k4.w;
        #pragma unroll
        for (int off = 16; off >= 1; off >>= 1) p += __shfl_xor_sync(0xffffffffu, p, off);
        if (lane == 0) g_S1[((size_t)i*BB + j)*SS + s] = p;
    }
}

// ---------------- K4: main banded kernel ----------------
// block = (chunk c, j, i); 256 threads; D-tile 64(s) x 128(t), K-depth 128.
__global__ __launch_bounds__(256, 2) void k_main(const float* __restrict__ qm,
                                                 const float* __restrict__ km) {
    extern __shared__ float sm[];
    float* Kt  = sm;                    // [HH][TW] keys transposed
    float* Qt  = sm + HH*TW;            // [HH][SC] queries transposed
    float* kmw = Qt + HH*SC;            // [TW]
    float* qms = kmw + TW;              // [SC]
    float* wt  = qms + SC;              // [TT+4]
    float* red = wt + (TT+4);           // [16]

    int c = blockIdx.x, j = blockIdx.y, i = blockIdx.z;
    int tid = threadIdx.x;
    int t0 = c*SC - TT;                 // global t at window col 0
    int s0 = c*SC;

    // stage K window (zero-padded, transposed [h][t])
    for (int idx = tid; idx < TW*(HH/4); idx += 256) {
        int t = idx & (TW-1); int h4 = idx >> 7;
        int tg = t0 + t;
        float4 v = make_float4(0.f, 0.f, 0.f, 0.f);
        if (tg >= 0 && tg < SS)
            v = *reinterpret_cast<const float4*>(&g_kn[((size_t)j*SS + tg)*HH + h4*4]);
        Kt[(h4*4+0)*TW + t] = v.x;
        Kt[(h4*4+1)*TW + t] = v.y;
        Kt[(h4*4+2)*TW + t] = v.z;
        Kt[(h4*4+3)*TW + t] = v.w;
    }
    // stage Q chunk (transposed [h][s])
    for (int idx = tid; idx < SC*(HH/4); idx += 256) {
        int s = idx & (SC-1); int h4 = idx >> 6;
        float4 v = *reinterpret_cast<const float4*>(&g_qn[((size_t)i*SS + s0 + s)*HH + h4*4]);
        Qt[(h4*4+0)*SC + s] = v.x;
        Qt[(h4*4+1)*SC + s] = v.y;
        Qt[(h4*4+2)*SC + s] = v.z;
        Qt[(h4*4+3)*SC + s] = v.w;
    }
    if (tid < TW) { int tg = t0 + tid; kmw[tid] = (tg >= 0 && tg < SS) ? km[j*SS + tg] : 0.f; }
    if (tid < SC) qms[tid] = qm[i*SS + s0 + tid];
    if (tid <= TT) wt[tid] = g_wtab[tid];
    __syncthreads();

    // GEMM: thread micro-tile 4(s) x 8(t), accumulated as 4x4 packed f32x2
    int tg_ = tid & 15;                 // t-group: 8 t each
    int sg_ = tid >> 4;                 // s-group: 4 s each
    const float* qcol = Qt + sg_*4;
    const float* kcol = Kt + tg_*8;
    unsigned long long acc[4][4];
    #pragma unroll
    for (int a = 0; a < 4; a++)
        #pragma unroll
        for (int b = 0; b < 4; b++) acc[a][b] = 0ull;

    #pragma unroll 8
    for (int h = 0; h < HH; h++) {
        float4 av = *reinterpret_cast<const float4*>(qcol + h*SC);
        ulonglong2 b01 = *reinterpret_cast<const ulonglong2*>(kcol + h*TW);
        ulonglong2 b23 = *reinterpret_cast<const ulonglong2*>(kcol + h*TW + 4);
        unsigned long long aa0, aa1, aa2, aa3;
        PACK2(aa0, av.x); PACK2(aa1, av.y); PACK2(aa2, av.z); PACK2(aa3, av.w);
        FFMA2(acc[0][0], aa0, b01.x); FFMA2(acc[0][1], aa0, b01.y);
        FFMA2(acc[0][2], aa0, b23.x); FFMA2(acc[0][3], aa0, b23.y);
        FFMA2(acc[1][0], aa1, b01.x); FFMA2(acc[1][1], aa1, b01.y);
        FFMA2(acc[1][2], aa1, b23.x); FFMA2(acc[1][3], aa1, b23.y);
        FFMA2(acc[2][0], aa2, b01.x); FFMA2(acc[2][1], aa2, b01.y);
        FFMA2(acc[2][2], aa2, b23.x); FFMA2(acc[2][3], aa2, b23.y);
        FFMA2(acc[3][0], aa3, b01.x); FFMA2(acc[3][1], aa3, b01.y);
        FFMA2(acc[3][2], aa3, b23.x); FFMA2(acc[3][3], aa3, b23.y);
    }

    // Epilogue: per-s band sums. delta = t_glob - s_glob = tl - sl - TT.
    float En[4] = {0,0,0,0}, Nn[4] = {0,0,0,0}, Sd[4] = {0,0,0,0}, Cn[4] = {0,0,0,0};
    #pragma unroll
    for (int si = 0; si < 4; si++) {
        int sl = sg_*4 + si;
        #pragma unroll
        for (int p = 0; p < 4; p++) {
            float d0, d1; UNPACK2(d0, d1, acc[si][p]);
            int tl = tg_*8 + p*2;
            {
                int ad = abs(tl - sl - TT);
                float kmv = kmw[tl];
                if (ad <= TT && kmv > 0.999f) {
                    float e = __expf(d0 * wt[ad]);
                    En[si] += e; Nn[si] += e*d0; Sd[si] += d0; Cn[si] += 1.f;
                }
            }
            {
                int ad = abs(tl + 1 - sl - TT);
                float kmv = kmw[tl + 1];
                if (ad <= TT && kmv > 0.999f) {
                    float e = __expf(d1 * wt[ad]);
                    En[si] += e; Nn[si] += e*d1; Sd[si] += d1; Cn[si] += 1.f;
                }
            }
        }
    }
    // reduce across the 16 threads sharing an s-group (lanes 0-15 / 16-31)
    #pragma unroll
    for (int si = 0; si < 4; si++) {
        #pragma unroll
        for (int off = 8; off >= 1; off >>= 1) {
            En[si] += __shfl_xor_sync(0xffffffffu, En[si], off);
            Nn[si] += __shfl_xor_sync(0xffffffffu, Nn[si], off);
            Sd[si] += __shfl_xor_sync(0xffffffffu, Sd[si], off);
            Cn[si] += __shfl_xor_sync(0xffffffffu, Cn[si], off);
        }
    }
    if (tg_ == 0) {
        float kc = g_kcnt[j];
        float local = 0.f;
        #pragma unroll
        for (int si = 0; si < 4; si++) {
            int sl = sg_*4 + si;
            float S1v = g_S1[((size_t)i*BB + j)*SS + (s0 + sl)];
            float Z   = En[si] + (kc - Cn[si]);          // far terms: e^{dw} ~= 1
            float Nm  = Nn[si] + (S1v - Sd[si]);         // far terms: d*e^{dw} ~= d
            float scv = (Z > 1e-12f) ? (Nm / Z) : 0.f;
            local += qms[sl] * scv;
        }
        red[sg_] = local;
    }
    __syncthreads();
    if (tid == 0) {
        float sum = 0.f;
        #pragma unroll
        for (int x = 0; x < 16; x++) sum += red[x];
        g_partial[((size_t)i*BB + j)*NC + c] = sum;
    }
}

// ---------------- K5: final reduce ----------------
__global__ void k_final(float* __restrict__ out) {
    int tid = threadIdx.x;                 // 256 = (i,j)
    float s = 0.f;
    #pragma unroll
    for (int c = 0; c < NC; c++) s += g_partial[tid*NC + c];
    out[tid] = s / g_qdenom[tid >> 4];
}

// ---------------- launch ----------------
extern "C" void kernel_launch(void* const* d_in, const int* in_sizes, int n_in,
                              void* d_out, int out_size) {
    const float* qe = (const float*)d_in[0];
    const float* ke = (const float*)d_in[1];
    const float* qm = (const float*)d_in[2];
    const float* km = (const float*)d_in[3];
    float* out = (float*)d_out;

    const int SMEM = (HH*TW + HH*SC + TW + SC + (TT+4) + 16) * (int)sizeof(float);
    cudaFuncSetAttribute(k_main, cudaFuncAttributeMaxDynamicSharedMemorySize, SMEM);

    k_norm <<<(2*BB*SS)/8, 256>>>(qe, ke);
    k_prep <<<BB, 128>>>(km, qm);
    k_s1   <<<(BB*SS)/8, 256>>>();
    k_main <<<dim3(NC, BB, BB), 256, SMEM>>>(qm, km);
    k_final<<<1, 256>>>(out);
}

// round 3
// speedup vs baseline: 1.2326x; 1.2326x over previous
#include <cuda_runtime.h>
#include <math.h>

// Problem constants (fixed by the reference setup_inputs)
#define BB 16      // batch (both sides)
#define SS 512     // sequence length
#define HH 128     // hidden
#define TT 32      // band half-width: w(delta>32) <= 6.9e-8 -> linearized exactly enough
#define SC 64      // s-chunk per block in main kernel
#define TW 128     // t-window per block = SC + 2*TT
#define NC (SS/SC) // 8 chunks
#define KROW (TW + (TW/32)*4)   // 144: +4 floats pad per 32 -> conflict-free 8-stride LDS.128

// ---------------- device scratch (no allocations allowed) ----------------
__device__ float g_qn[BB*SS*HH];     // normalized queries
__device__ float g_kn[BB*SS*HH];     // normalized keys
__device__ float g_ksum[BB*HH];      // per-j masked sum of normalized keys
__device__ float g_kcnt[BB];         // per-j count of valid keys
__device__ float g_qdenom[BB];       // per-i max(sum(q_mask),1)
__device__ float g_S1[BB*BB*SS];     // S1[i][j][s] = qhat_s . ksum_j
__device__ float g_partial[BB*BB*NC];
__device__ float g_wtab[TT+1];       // exp(-0.5*delta)

// ---------------- packed f32x2 helpers (sm_100a) ----------------
#define FFMA2(d,a,b) asm("fma.rn.f32x2 %0, %1, %2, %0;" : "+l"(d) : "l"(a), "l"(b))
#define PACK2(d,x)   asm("mov.b64 %0, {%1, %1};" : "=l"(d) : "r"(__float_as_uint(x)))
#define UNPACK2(lo,hi,d) do { unsigned int _u0,_u1; \
    asm("mov.b64 {%0, %1}, %2;" : "=r"(_u0), "=r"(_u1) : "l"(d)); \
    lo = __uint_as_float(_u0); hi = __uint_as_float(_u1); } while(0)

__device__ __forceinline__ int scol(int t) { return t + ((t >> 5) << 2); }

// ---------------- K1: L2-normalize q and k rows ----------------
__global__ void k_norm(const float* __restrict__ qe, const float* __restrict__ ke) {
    int row  = blockIdx.x * 8 + (threadIdx.x >> 5);   // 8 warps per block, 1 row/warp
    int lane = threadIdx.x & 31;
    const float* src; float* dst;
    if (row < BB*SS) { src = qe + (size_t)row*HH; dst = g_qn + (size_t)row*HH; }
    else             { int r = row - BB*SS; src = ke + (size_t)r*HH; dst = g_kn + (size_t)r*HH; }
    float4 v = reinterpret_cast<const float4*>(src)[lane];
    float ss = v.x*v.x + v.y*v.y + v.z*v.z + v.w*v.w;
    #pragma unroll
    for (int off = 16; off >= 1; off >>= 1) ss += __shfl_xor_sync(0xffffffffu, ss, off);
    float sc = 1.0f / fmaxf(sqrtf(ss), 1e-12f);
    v.x *= sc; v.y *= sc; v.z *= sc; v.w *= sc;
    reinterpret_cast<float4*>(dst)[lane] = v;
}

// ---------------- K2: per-j masked key sums, counts, denoms, w-table ----------------
__global__ void k_prep(const float* __restrict__ km, const float* __restrict__ qm) {
    __shared__ float kms[SS];
    __shared__ float qmsm[SS];
    __shared__ float reda[4], redb[4];
    int j = blockIdx.x, tid = threadIdx.x;   // 128 threads
    for (int t = tid; t < SS; t += 128) {
        // binary-gate key mask (matches exp(-(1-v)*1e9)=0 for any v<1)
        kms[t]  = (km[j*SS + t] > 0.999f) ? 1.0f : 0.0f;
        qmsm[t] = qm[j*SS + t];
    }
    __syncthreads();
    float acc = 0.0f;
    #pragma unroll 4
    for (int t = 0; t < SS; t++) acc += g_kn[((size_t)j*SS + t)*HH + tid] * kms[t];
    g_ksum[j*HH + tid] = acc;
    // parallel count reductions
    float a = 0.f, b = 0.f;
    for (int t = tid; t < SS; t += 128) { a += kms[t]; b += qmsm[t]; }
    #pragma unroll
    for (int off = 16; off >= 1; off >>= 1) {
        a += __shfl_xor_sync(0xffffffffu, a, off);
        b += __shfl_xor_sync(0xffffffffu, b, off);
    }
    if ((tid & 31) == 0) { reda[tid >> 5] = a; redb[tid >> 5] = b; }
    __syncthreads();
    if (tid == 0) {
        float sa = reda[0]+reda[1]+reda[2]+reda[3];
        float sb = redb[0]+redb[1]+redb[2]+redb[3];
        g_kcnt[j] = sa;
        g_qdenom[j] = fmaxf(sb, 1.0f);
    }
    if (blockIdx.x == 0 && tid <= TT) g_wtab[tid] = expf(-0.5f * (float)tid);
}

// ---------------- K3: S1[i][j][s] = qhat_s . ksum_j ----------------
__global__ void k_s1() {
    __shared__ float ks[BB*HH];
    int tid = threadIdx.x;
    for (int x = tid; x < BB*HH; x += 256) ks[x] = g_ksum[x];
    __syncthreads();
    int w = tid >> 5, lane = tid & 31;
    int row = blockIdx.x * 8 + w;            // 0..8191
    int i = row >> 9, s = row & (SS-1);
    float4 q = *reinterpret_cast<const float4*>(&g_qn[(size_t)row*HH + lane*4]);
    #pragma unroll
    for (int j = 0; j < BB; j++) {
        float4 k4 = *reinterpret_cast<const float4*>(&ks[j*HH + lane*4]);
        float p = q.x*k4.x + q.y*k4.y + q.z*k4.z + q.w*k4.w;
        #pragma unroll
        for (int off = 16; off >= 1; off >>= 1) p += __shfl_xor_sync(0xffffffffu, p, off);
        if (lane == 0) g_S1[((size_t)i*BB + j)*SS + s] = p;
    }
}

// ---------------- K4: main banded kernel ----------------
// block = (chunk c, j, i); 128 threads; D-tile 64(s) x 128(t), K-depth 128.
// micro-tile 8(s) x 8(t) per thread; K stored padded (conflict-free 8-stride).
__global__ __launch_bounds__(128, 2) void k_main(const float* __restrict__ qm,
                                                 const float* __restrict__ km) {
    extern __shared__ float sm[];
    float* Kt  = sm;                    // [HH][KROW] keys transposed, padded
    float* Qt  = sm + HH*KROW;          // [HH][SC] queries transposed
    float* kmw = Qt + HH*SC;            // [TW]
    float* qms = kmw + TW;              // [SC]
    float* wt  = qms + SC;              // [TT+4]
    float* red = wt + (TT+4);           // [8]

    int c = blockIdx.x, j = blockIdx.y, i = blockIdx.z;
    int tid = threadIdx.x;
    int t0 = c*SC - TT;                 // global t at window col 0
    int s0 = c*SC;

    // stage K window (zero-padded, transposed [h][scol(t)])
    for (int idx = tid; idx < TW*(HH/4); idx += 128) {
        int t = idx & (TW-1); int h4 = idx >> 7;
        int tg = t0 + t;
        float4 v = make_float4(0.f, 0.f, 0.f, 0.f);
        if (tg >= 0 && tg < SS)
            v = *reinterpret_cast<const float4*>(&g_kn[((size_t)j*SS + tg)*HH + h4*4]);
        int tc = scol(t);
        Kt[(h4*4+0)*KROW + tc] = v.x;
        Kt[(h4*4+1)*KROW + tc] = v.y;
        Kt[(h4*4+2)*KROW + tc] = v.z;
        Kt[(h4*4+3)*KROW + tc] = v.w;
    }
    // stage Q chunk (transposed [h][s])
    for (int idx = tid; idx < SC*(HH/4); idx += 128) {
        int s = idx & (SC-1); int h4 = idx >> 6;
        float4 v = *reinterpret_cast<const float4*>(&g_qn[((size_t)i*SS + s0 + s)*HH + h4*4]);
        Qt[(h4*4+0)*SC + s] = v.x;
        Qt[(h4*4+1)*SC + s] = v.y;
        Qt[(h4*4+2)*SC + s] = v.z;
        Qt[(h4*4+3)*SC + s] = v.w;
    }
    if (tid < TW) { int tg = t0 + tid; kmw[tid] = (tg >= 0 && tg < SS) ? km[j*SS + tg] : 0.f; }
    if (tid < SC) qms[tid] = qm[i*SS + s0 + tid];
    if (tid <= TT) wt[tid] = g_wtab[tid];
    __syncthreads();

    // GEMM: thread micro-tile 8(s) x 8(t), accumulated as 8x4 packed f32x2
    int tg_ = tid & 15;                 // t-group: 8 t each (16 groups)
    int sg_ = tid >> 4;                 // s-group: 8 s each (8 groups)
    const float* qcol = Qt + sg_*8;
    const float* kcol = Kt + scol(tg_*8);
    unsigned long long acc[8][4];
    #pragma unroll
    for (int a = 0; a < 8; a++)
        #pragma unroll
        for (int b = 0; b < 4; b++) acc[a][b] = 0ull;

    #pragma unroll 4
    for (int h = 0; h < HH; h++) {
        const float* qp = qcol + h*SC;
        const float* kp = kcol + h*KROW;
        float4 a0 = *reinterpret_cast<const float4*>(qp);
        float4 a1 = *reinterpret_cast<const float4*>(qp + 4);
        ulonglong2 b01 = *reinterpret_cast<const ulonglong2*>(kp);
        ulonglong2 b23 = *reinterpret_cast<const ulonglong2*>(kp + 4);
        unsigned long long A0,A1,A2,A3,A4,A5,A6,A7;
        PACK2(A0, a0.x); PACK2(A1, a0.y); PACK2(A2, a0.z); PACK2(A3, a0.w);
        PACK2(A4, a1.x); PACK2(A5, a1.y); PACK2(A6, a1.z); PACK2(A7, a1.w);
        FFMA2(acc[0][0], A0, b01.x); FFMA2(acc[0][1], A0, b01.y);
        FFMA2(acc[0][2], A0, b23.x); FFMA2(acc[0][3], A0, b23.y);
        FFMA2(acc[1][0], A1, b01.x); FFMA2(acc[1][1], A1, b01.y);
        FFMA2(acc[1][2], A1, b23.x); FFMA2(acc[1][3], A1, b23.y);
        FFMA2(acc[2][0], A2, b01.x); FFMA2(acc[2][1], A2, b01.y);
        FFMA2(acc[2][2], A2, b23.x); FFMA2(acc[2][3], A2, b23.y);
        FFMA2(acc[3][0], A3, b01.x); FFMA2(acc[3][1], A3, b01.y);
        FFMA2(acc[3][2], A3, b23.x); FFMA2(acc[3][3], A3, b23.y);
        FFMA2(acc[4][0], A4, b01.x); FFMA2(acc[4][1], A4, b01.y);
        FFMA2(acc[4][2], A4, b23.x); FFMA2(acc[4][3], A4, b23.y);
        FFMA2(acc[5][0], A5, b01.x); FFMA2(acc[5][1], A5, b01.y);
        FFMA2(acc[5][2], A5, b23.x); FFMA2(acc[5][3], A5, b23.y);
        FFMA2(acc[6][0], A6, b01.x); FFMA2(acc[6][1], A6, b01.y);
        FFMA2(acc[6][2], A6, b23.x); FFMA2(acc[6][3], A6, b23.y);
        FFMA2(acc[7][0], A7, b01.x); FFMA2(acc[7][1], A7, b01.y);
        FFMA2(acc[7][2], A7, b23.x); FFMA2(acc[7][3], A7, b23.y);
    }

    // Epilogue: per-s band sums. delta = t_glob - s_glob = tl - sl - TT.
    float En[8], Nn[8], Sd[8], Cn[8];
    #pragma unroll
    for (int si = 0; si < 8; si++) { En[si]=0.f; Nn[si]=0.f; Sd[si]=0.f; Cn[si]=0.f; }
    #pragma unroll
    for (int si = 0; si < 8; si++) {
        int sl = sg_*8 + si;
        #pragma unroll
        for (int p = 0; p < 4; p++) {
            float d0, d1; UNPACK2(d0, d1, acc[si][p]);
            int tl = tg_*8 + p*2;
            {
                int ad = abs(tl - sl - TT);
                float kmv = kmw[tl];
                if (ad <= TT && kmv > 0.999f) {
                    float e = __expf(d0 * wt[ad]);
                    En[si] += e; Nn[si] += e*d0; Sd[si] += d0; Cn[si] += 1.f;
                }
            }
            {
                int ad = abs(tl + 1 - sl - TT);
                float kmv = kmw[tl + 1];
                if (ad <= TT && kmv > 0.999f) {
                    float e = __expf(d1 * wt[ad]);
                    En[si] += e; Nn[si] += e*d1; Sd[si] += d1; Cn[si] += 1.f;
                }
            }
        }
    }
    // reduce across the 16 threads sharing an s-group (lane halves)
    #pragma unroll
    for (int si = 0; si < 8; si++) {
        #pragma unroll
        for (int off = 8; off >= 1; off >>= 1) {
            En[si] += __shfl_xor_sync(0xffffffffu, En[si], off);
            Nn[si] += __shfl_xor_sync(0xffffffffu, Nn[si], off);
            Sd[si] += __shfl_xor_sync(0xffffffffu, Sd[si], off);
            Cn[si] += __shfl_xor_sync(0xffffffffu, Cn[si], off);
        }
    }
    if (tg_ == 0) {
        float kc = g_kcnt[j];
        float local = 0.f;
        #pragma unroll
        for (int si = 0; si < 8; si++) {
            int sl = sg_*8 + si;
            float S1v = g_S1[((size_t)i*BB + j)*SS + (s0 + sl)];
            float Z   = En[si] + (kc - Cn[si]);          // far terms: e^{dw} ~= 1
            float Nm  = Nn[si] + (S1v - Sd[si]);         // far terms: d*e^{dw} ~= d
            float scv = (Z > 1e-12f) ? (Nm / Z) : 0.f;
            local += qms[sl] * scv;
        }
        red[sg_] = local;
    }
    __syncthreads();
    if (tid == 0) {
        float sum = 0.f;
        #pragma unroll
        for (int x = 0; x < 8; x++) sum += red[x];
        g_partial[((size_t)i*BB + j)*NC + c] = sum;
    }
}

// ---------------- K5: final reduce ----------------
__global__ void k_final(float* __restrict__ out) {
    int tid = threadIdx.x;                 // 256 = (i,j)
    float s = 0.f;
    #pragma unroll
    for (int c = 0; c < NC; c++) s += g_partial[tid*NC + c];
    out[tid] = s / g_qdenom[tid >> 4];
}

// ---------------- launch ----------------
extern "C" void kernel_launch(void* const* d_in, const int* in_sizes, int n_in,
                              void* d_out, int out_size) {
    const float* qe = (const float*)d_in[0];
    const float* ke = (const float*)d_in[1];
    const float* qm = (const float*)d_in[2];
    const float* km = (const float*)d_in[3];
    float* out = (float*)d_out;

    const int SMEM = (HH*KROW + HH*SC + TW + SC + (TT+4) + 8) * (int)sizeof(float);
    cudaFuncSetAttribute(k_main, cudaFuncAttributeMaxDynamicSharedMemorySize, SMEM);

    k_norm <<<(2*BB*SS)/8, 256>>>(qe, ke);
    k_prep <<<BB, 128>>>(km, qm);
    k_s1   <<<(BB*SS)/8, 256>>>();
    k_main <<<dim3(NC, BB, BB), 128, SMEM>>>(qm, km);
    k_final<<<1, 256>>>(out);
}

// round 4
// speedup vs baseline: 1.3689x; 1.1105x over previous
#include <cuda_runtime.h>
#include <math.h>

// Problem constants (fixed by the reference setup_inputs)
#define BB 16      // batch (both sides)
#define SS 512     // sequence length
#define HH 128     // hidden
#define TT 32      // band half-width: w(delta>32) <= 6.9e-8 -> linearized exactly enough
#define SC 64      // s-chunk per block in main kernel
#define TW 128     // t-window per block = SC + 2*TT
#define NC (SS/SC) // 8 chunks
#define KROW (TW + (TW/32)*4)   // 144: +4 floats pad per 32 -> conflict-free 8-stride LDS.128

// ---------------- device scratch (no allocations allowed) ----------------
__device__ float g_qn[BB*SS*HH];     // normalized queries
__device__ float g_kn[BB*SS*HH];     // normalized keys
__device__ float g_ksum4[BB*4*HH];   // per-(j, t-quarter) masked key sums
__device__ float g_cnt4[BB*4*2];     // per-(j, quarter) {kcnt, qmask-sum} partials
__device__ float g_kcnt[BB];         // per-j count of valid keys
__device__ float g_qdenom[BB];       // per-i max(sum(q_mask),1)
__device__ float g_S1[BB*BB*SS];     // S1[i][j][s] = qhat_s . ksum_j
__device__ float g_partial[BB*BB*NC];
__device__ float g_wtab[TT+1];       // exp(-0.5*delta)

// ---------------- packed f32x2 helpers (sm_100a) ----------------
#define FFMA2(d,a,b) asm("fma.rn.f32x2 %0, %1, %2, %0;" : "+l"(d) : "l"(a), "l"(b))
#define ADD2(d,o)    asm("add.rn.f32x2 %0, %0, %1;" : "+l"(d) : "l"(o))
#define PACK2(d,x)   asm("mov.b64 %0, {%1, %1};" : "=l"(d) : "r"(__float_as_uint(x)))
#define UNPACK2(lo,hi,d) do { unsigned int _u0,_u1; \
    asm("mov.b64 {%0, %1}, %2;" : "=r"(_u0), "=r"(_u1) : "l"(d)); \
    lo = __uint_as_float(_u0); hi = __uint_as_float(_u1); } while(0)

__device__ __forceinline__ int scol(int t) { return t + ((t >> 5) << 2); }

// ---------------- K1: L2-normalize q and k rows ----------------
__global__ void k_norm(const float* __restrict__ qe, const float* __restrict__ ke) {
    int row  = blockIdx.x * 8 + (threadIdx.x >> 5);   // 8 warps per block, 1 row/warp
    int lane = threadIdx.x & 31;
    const float* src; float* dst;
    if (row < BB*SS) { src = qe + (size_t)row*HH; dst = g_qn + (size_t)row*HH; }
    else             { int r = row - BB*SS; src = ke + (size_t)r*HH; dst = g_kn + (size_t)r*HH; }
    float4 v = reinterpret_cast<const float4*>(src)[lane];
    float ss = v.x*v.x + v.y*v.y + v.z*v.z + v.w*v.w;
    #pragma unroll
    for (int off = 16; off >= 1; off >>= 1) ss += __shfl_xor_sync(0xffffffffu, ss, off);
    float sc = 1.0f / fmaxf(sqrtf(ss), 1e-12f);
    v.x *= sc; v.y *= sc; v.z *= sc; v.w *= sc;
    reinterpret_cast<float4*>(dst)[lane] = v;
}

// ---------------- K2: per-(j, t-quarter) masked key sums + count partials ----------------
__global__ void k_prep(const float* __restrict__ km, const float* __restrict__ qm) {
    __shared__ float kms[128];
    __shared__ float reda[4], redb[4];
    int b = blockIdx.x;           // 64 blocks = (j, quarter)
    int j = b >> 2, q = b & 3;
    int tid = threadIdx.x;        // 128 threads
    int tbase = q * 128;
    // binary-gate key mask (matches exp(-(1-v)*1e9)=0 for any v<1)
    float kmv = (km[j*SS + tbase + tid] > 0.999f) ? 1.0f : 0.0f;
    float qmv = qm[j*SS + tbase + tid];
    kms[tid] = kmv;
    __syncthreads();
    float acc = 0.0f;
    #pragma unroll 4
    for (int t = 0; t < 128; t++)
        acc += g_kn[((size_t)j*SS + tbase + t)*HH + tid] * kms[t];
    g_ksum4[(size_t)b*HH + tid] = acc;
    // partial count reductions
    float a = kmv, b2 = qmv;
    #pragma unroll
    for (int off = 16; off >= 1; off >>= 1) {
        a  += __shfl_xor_sync(0xffffffffu, a, off);
        b2 += __shfl_xor_sync(0xffffffffu, b2, off);
    }
    if ((tid & 31) == 0) { reda[tid >> 5] = a; redb[tid >> 5] = b2; }
    __syncthreads();
    if (tid == 0) {
        g_cnt4[b*2 + 0] = reda[0]+reda[1]+reda[2]+reda[3];
        g_cnt4[b*2 + 1] = redb[0]+redb[1]+redb[2]+redb[3];
    }
    if (b == 0 && tid <= TT) g_wtab[tid] = expf(-0.5f * (float)tid);
}

// ---------------- K3: S1[i][j][s] = qhat_s . ksum_j; finalize counts ----------------
__global__ void k_s1() {
    __shared__ float ks[BB*HH];
    int tid = threadIdx.x;
    for (int x = tid; x < BB*HH; x += 256) {
        int jj = x >> 7, hh = x & (HH-1);
        float v = 0.f;
        #pragma unroll
        for (int p = 0; p < 4; p++) v += g_ksum4[((size_t)jj*4 + p)*HH + hh];
        ks[x] = v;
    }
    if (blockIdx.x == 0 && tid < BB) {
        float a = 0.f, b = 0.f;
        #pragma unroll
        for (int p = 0; p < 4; p++) { a += g_cnt4[(tid*4+p)*2+0]; b += g_cnt4[(tid*4+p)*2+1]; }
        g_kcnt[tid]   = a;
        g_qdenom[tid] = fmaxf(b, 1.0f);
    }
    __syncthreads();
    int w = tid >> 5, lane = tid & 31;
    int row = blockIdx.x * 8 + w;            // 0..8191
    int i = row >> 9, s = row & (SS-1);
    float4 q = *reinterpret_cast<const float4*>(&g_qn[(size_t)row*HH + lane*4]);
    #pragma unroll
    for (int j = 0; j < BB; j++) {
        float4 k4 = *reinterpret_cast<const float4*>(&ks[j*HH + lane*4]);
        float p = q.x*k4.x + q.y*k4.y + q.z*k4.z + q.w*k4.w;
        #pragma unroll
        for (int off = 16; off >= 1; off >>= 1) p += __shfl_xor_sync(0xffffffffu, p, off);
        if (lane == 0) g_S1[((size_t)i*BB + j)*SS + s] = p;
    }
}

// ---------------- K4: main banded kernel (split-K over thread halves) ----------------
// block = (chunk c, j, i); 256 threads; D-tile 64(s) x 128(t), K-depth 128 split 2x64.
// micro-tile 8(s) x 8(t) per thread; K stored padded (conflict-free 8-stride).
__global__ __launch_bounds__(256, 2) void k_main(const float* __restrict__ qm,
                                                 const float* __restrict__ km) {
    extern __shared__ float sm[];
    float* Kt  = sm;                    // [HH][KROW] keys transposed, padded
    float* Qt  = sm + HH*KROW;          // [HH][SC] queries transposed (reused as EX)
    float* kmw = Qt + HH*SC;            // [TW]
    float* qms = kmw + TW;              // [SC]
    float* wt  = qms + SC;              // [TT+4]
    float* red = wt + (TT+4);           // [8]

    int c = blockIdx.x, j = blockIdx.y, i = blockIdx.z;
    int tid = threadIdx.x;
    int half = tid >> 7;
    int t128 = tid & 127;
    int t0 = c*SC - TT;                 // global t at window col 0
    int s0 = c*SC;

    // stage K window (zero-padded, transposed [h][scol(t)])
    for (int idx = tid; idx < TW*(HH/4); idx += 256) {
        int t = idx & (TW-1); int h4 = idx >> 7;
        int tg = t0 + t;
        float4 v = make_float4(0.f, 0.f, 0.f, 0.f);
        if (tg >= 0 && tg < SS)
            v = *reinterpret_cast<const float4*>(&g_kn[((size_t)j*SS + tg)*HH + h4*4]);
        int tc = scol(t);
        Kt[(h4*4+0)*KROW + tc] = v.x;
        Kt[(h4*4+1)*KROW + tc] = v.y;
        Kt[(h4*4+2)*KROW + tc] = v.z;
        Kt[(h4*4+3)*KROW + tc] = v.w;
    }
    // stage Q chunk (transposed [h][s])
    for (int idx = tid; idx < SC*(HH/4); idx += 256) {
        int s = idx & (SC-1); int h4 = idx >> 6;
        float4 v = *reinterpret_cast<const float4*>(&g_qn[((size_t)i*SS + s0 + s)*HH + h4*4]);
        Qt[(h4*4+0)*SC + s] = v.x;
        Qt[(h4*4+1)*SC + s] = v.y;
        Qt[(h4*4+2)*SC + s] = v.z;
        Qt[(h4*4+3)*SC + s] = v.w;
    }
    if (tid < TW) { int tg = t0 + tid; kmw[tid] = (tg >= 0 && tg < SS) ? km[j*SS + tg] : 0.f; }
    if (tid >= 128 && tid < 128+SC) qms[tid-128] = qm[i*SS + s0 + (tid-128)];
    if (tid >= 192 && tid <= 192+TT) wt[tid-192] = g_wtab[tid-192];
    __syncthreads();

    // GEMM: thread micro-tile 8(s) x 8(t); half 0 -> h[0,64), half 1 -> h[64,128)
    int tg_ = t128 & 15;                // t-group: 8 t each (16 groups)
    int sg_ = t128 >> 4;                // s-group: 8 s each (8 groups)
    const float* qcol = Qt + sg_*8 + (half << 6)*SC;
    const float* kcol = Kt + scol(tg_*8) + (half << 6)*KROW;
    unsigned long long acc[8][4];
    #pragma unroll
    for (int a = 0; a < 8; a++)
        #pragma unroll
        for (int b = 0; b < 4; b++) acc[a][b] = 0ull;

    #pragma unroll 4
    for (int h = 0; h < 64; h++) {
        const float* qp = qcol + h*SC;
        const float* kp = kcol + h*KROW;
        float4 a0 = *reinterpret_cast<const float4*>(qp);
        float4 a1 = *reinterpret_cast<const float4*>(qp + 4);
        ulonglong2 b01 = *reinterpret_cast<const ulonglong2*>(kp);
        ulonglong2 b23 = *reinterpret_cast<const ulonglong2*>(kp + 4);
        unsigned long long A0,A1,A2,A3,A4,A5,A6,A7;
        PACK2(A0, a0.x); PACK2(A1, a0.y); PACK2(A2, a0.z); PACK2(A3, a0.w);
        PACK2(A4, a1.x); PACK2(A5, a1.y); PACK2(A6, a1.z); PACK2(A7, a1.w);
        FFMA2(acc[0][0], A0, b01.x); FFMA2(acc[0][1], A0, b01.y);
        FFMA2(acc[0][2], A0, b23.x); FFMA2(acc[0][3], A0, b23.y);
        FFMA2(acc[1][0], A1, b01.x); FFMA2(acc[1][1], A1, b01.y);
        FFMA2(acc[1][2], A1, b23.x); FFMA2(acc[1][3], A1, b23.y);
        FFMA2(acc[2][0], A2, b01.x); FFMA2(acc[2][1], A2, b01.y);
        FFMA2(acc[2][2], A2, b23.x); FFMA2(acc[2][3], A2, b23.y);
        FFMA2(acc[3][0], A3, b01.x); FFMA2(acc[3][1], A3, b01.y);
        FFMA2(acc[3][2], A3, b23.x); FFMA2(acc[3][3], A3, b23.y);
        FFMA2(acc[4][0], A4, b01.x); FFMA2(acc[4][1], A4, b01.y);
        FFMA2(acc[4][2], A4, b23.x); FFMA2(acc[4][3], A4, b23.y);
        FFMA2(acc[5][0], A5, b01.x); FFMA2(acc[5][1], A5, b01.y);
        FFMA2(acc[5][2], A5, b23.x); FFMA2(acc[5][3], A5, b23.y);
        FFMA2(acc[6][0], A6, b01.x); FFMA2(acc[6][1], A6, b01.y);
        FFMA2(acc[6][2], A6, b23.x); FFMA2(acc[6][3], A6, b23.y);
        FFMA2(acc[7][0], A7, b01.x); FFMA2(acc[7][1], A7, b01.y);
        FFMA2(acc[7][2], A7, b23.x); FFMA2(acc[7][3], A7, b23.y);
    }
    __syncthreads();                    // Qt reads complete; safe to reuse as EX

    // merge halves: upper half spills packed accs (interleaved, conflict-free)
    unsigned long long* EX = reinterpret_cast<unsigned long long*>(Qt);
    if (half) {
        #pragma unroll
        for (int a = 0; a < 8; a++)
            #pragma unroll
            for (int b = 0; b < 4; b++)
                EX[(a*4 + b)*128 + t128] = acc[a][b];
    }
    __syncthreads();

    if (half == 0) {
        #pragma unroll
        for (int a = 0; a < 8; a++)
            #pragma unroll
            for (int b = 0; b < 4; b++) {
                unsigned long long o = EX[(a*4 + b)*128 + t128];
                ADD2(acc[a][b], o);
            }

        // Epilogue: per-s band sums. delta = t_glob - s_glob = tl - sl - TT.
        float En[8], Nn[8], Sd[8], Cn[8];
        #pragma unroll
        for (int si = 0; si < 8; si++) { En[si]=0.f; Nn[si]=0.f; Sd[si]=0.f; Cn[si]=0.f; }
        #pragma unroll
        for (int si = 0; si < 8; si++) {
            int sl = sg_*8 + si;
            #pragma unroll
            for (int p = 0; p < 4; p++) {
                float d0, d1; UNPACK2(d0, d1, acc[si][p]);
                int tl = tg_*8 + p*2;
                {
                    int ad = abs(tl - sl - TT);
                    float kmv = kmw[tl];
                    if (ad <= TT && kmv > 0.999f) {
                        float e = __expf(d0 * wt[ad]);
                        En[si] += e; Nn[si] += e*d0; Sd[si] += d0; Cn[si] += 1.f;
                    }
                }
                {
                    int ad = abs(tl + 1 - sl - TT);
                    float kmv = kmw[tl + 1];
                    if (ad <= TT && kmv > 0.999f) {
                        float e = __expf(d1 * wt[ad]);
                        En[si] += e; Nn[si] += e*d1; Sd[si] += d1; Cn[si] += 1.f;
                    }
                }
            }
        }
        // reduce across the 16 threads sharing an s-group (lane halves)
        #pragma unroll
        for (int si = 0; si < 8; si++) {
            #pragma unroll
            for (int off = 8; off >= 1; off >>= 1) {
                En[si] += __shfl_xor_sync(0xffffffffu, En[si], off);
                Nn[si] += __shfl_xor_sync(0xffffffffu, Nn[si], off);
                Sd[si] += __shfl_xor_sync(0xffffffffu, Sd[si], off);
                Cn[si] += __shfl_xor_sync(0xffffffffu, Cn[si], off);
            }
        }
        if (tg_ == 0) {
            float kc = g_kcnt[j];
            float local = 0.f;
            #pragma unroll
            for (int si = 0; si < 8; si++) {
                int sl = sg_*8 + si;
                float S1v = g_S1[((size_t)i*BB + j)*SS + (s0 + sl)];
                float Z   = En[si] + (kc - Cn[si]);          // far terms: e^{dw} ~= 1
                float Nm  = Nn[si] + (S1v - Sd[si]);         // far terms: d*e^{dw} ~= d
                float scv = (Z > 1e-12f) ? (Nm / Z) : 0.f;
                local += qms[sl] * scv;
            }
            red[sg_] = local;
        }
    }
    __syncthreads();
    if (tid == 0) {
        float sum = 0.f;
        #pragma unroll
        for (int x = 0; x < 8; x++) sum += red[x];
        g_partial[((size_t)i*BB + j)*NC + c] = sum;
    }
}

// ---------------- K5: final reduce ----------------
__global__ void k_final(float* __restrict__ out) {
    int tid = threadIdx.x;                 // 256 = (i,j)
    float s = 0.f;
    #pragma unroll
    for (int c = 0; c < NC; c++) s += g_partial[tid*NC + c];
    out[tid] = s / g_qdenom[tid >> 4];
}

// ---------------- launch ----------------
extern "C" void kernel_launch(void* const* d_in, const int* in_sizes, int n_in,
                              void* d_out, int out_size) {
    const float* qe = (const float*)d_in[0];
    const float* ke = (const float*)d_in[1];
    const float* qm = (const float*)d_in[2];
    const float* km = (const float*)d_in[3];
    float* out = (float*)d_out;

    const int SMEM = (HH*KROW + HH*SC + TW + SC + (TT+4) + 8) * (int)sizeof(float);
    cudaFuncSetAttribute(k_main, cudaFuncAttributeMaxDynamicSharedMemorySize, SMEM);

    k_norm <<<(2*BB*SS)/8, 256>>>(qe, ke);
    k_prep <<<BB*4, 128>>>(km, qm);
    k_s1   <<<(BB*SS)/8, 256>>>();
    k_main <<<dim3(NC, BB, BB), 256, SMEM>>>(qm, km);
    k_final<<<1, 256>>>(out);
}

// round 6
// speedup vs baseline: 2.7168x; 1.9847x over previous
#include <cuda_runtime.h>
#include <cuda_bf16.h>
#include <math.h>
#include <cstdint>

// Problem constants
#define BB 16
#define SS 512
#define HH 128
#define TT 32
#define SC 64      // s-chunk (N of GEMM)
#define TW 128     // t-window (M of GEMM)
#define NC (SS/SC)
#define IGROUP 4   // i's per block

// smem byte offsets: K/Q tiles bf16 K-major, rows of 256B (16 chunks of 16B, XOR-swizzled)
#define SM_A_HI 0           // K-window hi [128][128] bf16 = 32768
#define SM_A_LO 32768
#define SM_B_HI 65536       // Q tile hi [64][128] bf16 = 16384
#define SM_B_LO 81920
#define SM_KMW  98304       // 128 floats
#define SM_WT   98816       // 33 floats (pad)
#define SM_PART 99072       // [8][64] float2 = 4096
#define SM_RED  103168      // 2 floats
#define SMEM_TOTAL 103200

// ---------------- device scratch ----------------
__device__ float g_qn[BB*SS*HH];
__device__ float g_kn[BB*SS*HH];
__device__ float g_ksum4[BB*4*HH];
__device__ float g_cnt4[BB*4*2];
__device__ float g_kcnt[BB];
__device__ float g_qdenom[BB];
__device__ float g_S1[BB*BB*SS];
__device__ float g_partial[BB*BB*NC];
__device__ float g_wtab[TT+1];

// ---------------- helpers ----------------
__device__ __forceinline__ uint32_t smem_u32(const void* p) {
    uint32_t a;
    asm("{ .reg .u64 t; cvta.to.shared.u64 t, %1; cvt.u32.u64 %0, t; }" : "=r"(a) : "l"(p));
    return a;
}

#define LDSM4(r0,r1,r2,r3,addr) \
    asm volatile("ldmatrix.sync.aligned.m8n8.x4.shared.b16 {%0,%1,%2,%3}, [%4];" \
        : "=r"(r0), "=r"(r1), "=r"(r2), "=r"(r3) : "r"(addr))

#define MMA16816(d, a0,a1,a2,a3, b0,b1) \
    asm volatile("mma.sync.aligned.m16n8k16.row.col.f32.bf16.bf16.f32 " \
        "{%0,%1,%2,%3}, {%4,%5,%6,%7}, {%8,%9}, {%0,%1,%2,%3};" \
        : "+f"((d)[0]), "+f"((d)[1]), "+f"((d)[2]), "+f"((d)[3]) \
        : "r"(a0), "r"(a1), "r"(a2), "r"(a3), "r"(b0), "r"(b1))

// bf16 hi/lo split of 8 floats -> two uint4 (bf16x2 packed)
__device__ __forceinline__ void split8(const float* v, uint4& hi, uint4& lo) {
    uint32_t h[4], l[4];
    #pragma unroll
    for (int p = 0; p < 4; p++) {
        float f0 = v[2*p], f1 = v[2*p+1];
        __nv_bfloat16 h0 = __float2bfloat16(f0), h1 = __float2bfloat16(f1);
        float r0 = f0 - __bfloat162float(h0), r1 = f1 - __bfloat162float(h1);
        __nv_bfloat162 hp(h0, h1);
        __nv_bfloat162 lp(__float2bfloat16(r0), __float2bfloat16(r1));
        h[p] = *reinterpret_cast<uint32_t*>(&hp);
        l[p] = *reinterpret_cast<uint32_t*>(&lp);
    }
    hi = make_uint4(h[0], h[1], h[2], h[3]);
    lo = make_uint4(l[0], l[1], l[2], l[3]);
}

// ---------------- K1: L2-normalize ----------------
__global__ void k_norm(const float* __restrict__ qe, const float* __restrict__ ke) {
    int row  = blockIdx.x * 8 + (threadIdx.x >> 5);
    int lane = threadIdx.x & 31;
    const float* src; float* dst;
    if (row < BB*SS) { src = qe + (size_t)row*HH; dst = g_qn + (size_t)row*HH; }
    else             { int r = row - BB*SS; src = ke + (size_t)r*HH; dst = g_kn + (size_t)r*HH; }
    float4 v = reinterpret_cast<const float4*>(src)[lane];
    float ss = v.x*v.x + v.y*v.y + v.z*v.z + v.w*v.w;
    #pragma unroll
    for (int off = 16; off >= 1; off >>= 1) ss += __shfl_xor_sync(0xffffffffu, ss, off);
    float sc = 1.0f / fmaxf(sqrtf(ss), 1e-12f);
    v.x *= sc; v.y *= sc; v.z *= sc; v.w *= sc;
    reinterpret_cast<float4*>(dst)[lane] = v;
}

// ---------------- K2: per-(j, quarter) masked key sums + counts ----------------
__global__ void k_prep(const float* __restrict__ km, const float* __restrict__ qm) {
    __shared__ float kms[128];
    __shared__ float reda[4], redb[4];
    int b = blockIdx.x;
    int j = b >> 2, q = b & 3;
    int tid = threadIdx.x;
    int tbase = q * 128;
    float kmv = (km[j*SS + tbase + tid] > 0.999f) ? 1.0f : 0.0f;
    float qmv = qm[j*SS + tbase + tid];
    kms[tid] = kmv;
    __syncthreads();
    float acc = 0.0f;
    #pragma unroll 4
    for (int t = 0; t < 128; t++)
        acc += g_kn[((size_t)j*SS + tbase + t)*HH + tid] * kms[t];
    g_ksum4[(size_t)b*HH + tid] = acc;
    float a = kmv, b2 = qmv;
    #pragma unroll
    for (int off = 16; off >= 1; off >>= 1) {
        a  += __shfl_xor_sync(0xffffffffu, a, off);
        b2 += __shfl_xor_sync(0xffffffffu, b2, off);
    }
    if ((tid & 31) == 0) { reda[tid >> 5] = a; redb[tid >> 5] = b2; }
    __syncthreads();
    if (tid == 0) {
        g_cnt4[b*2 + 0] = reda[0]+reda[1]+reda[2]+reda[3];
        g_cnt4[b*2 + 1] = redb[0]+redb[1]+redb[2]+redb[3];
    }
    if (b == 0 && tid <= TT) g_wtab[tid] = expf(-0.5f * (float)tid);
}

// ---------------- K3: S1 + finalize counts ----------------
__global__ void k_s1() {
    __shared__ float ks[BB*HH];
    int tid = threadIdx.x;
    for (int x = tid; x < BB*HH; x += 256) {
        int jj = x >> 7, hh = x & (HH-1);
        float v = 0.f;
        #pragma unroll
        for (int p = 0; p < 4; p++) v += g_ksum4[((size_t)jj*4 + p)*HH + hh];
        ks[x] = v;
    }
    if (blockIdx.x == 0 && tid < BB) {
        float a = 0.f, b = 0.f;
        #pragma unroll
        for (int p = 0; p < 4; p++) { a += g_cnt4[(tid*4+p)*2+0]; b += g_cnt4[(tid*4+p)*2+1]; }
        g_kcnt[tid]   = a;
        g_qdenom[tid] = fmaxf(b, 1.0f);
    }
    __syncthreads();
    int w = tid >> 5, lane = tid & 31;
    int row = blockIdx.x * 8 + w;
    int i = row >> 9, s = row & (SS-1);
    float4 q = *reinterpret_cast<const float4*>(&g_qn[(size_t)row*HH + lane*4]);
    #pragma unroll
    for (int j = 0; j < BB; j++) {
        float4 k4 = *reinterpret_cast<const float4*>(&ks[j*HH + lane*4]);
        float p = q.x*k4.x + q.y*k4.y + q.z*k4.z + q.w*k4.w;
        #pragma unroll
        for (int off = 16; off >= 1; off >>= 1) p += __shfl_xor_sync(0xffffffffu, p, off);
        if (lane == 0) g_S1[((size_t)i*BB + j)*SS + s] = p;
    }
}

// ---------------- K4: main banded kernel — mma.sync bf16 split GEMM ----------------
// block = (c, j, ig); loops 4 i's. D[t=128][s=64] = K_win * Q^T via 3 split passes.
// warp w owns t rows w*16..w*16+15 (full 64 s cols), m16n8k16 fragments.
__global__ __launch_bounds__(256) void k_main(const float* __restrict__ qm,
                                              const float* __restrict__ km) {
    extern __shared__ char smem[];
    uint32_t sb = smem_u32(smem);
    int c = blockIdx.x, j = blockIdx.y, ig = blockIdx.z;
    int tid = threadIdx.x;
    int wid = tid >> 5, lane = tid & 31;
    int t0 = c*SC - TT;
    int s0 = c*SC;

    float* kmw = reinterpret_cast<float*>(smem + SM_KMW);
    float* wt  = reinterpret_cast<float*>(smem + SM_WT);
    float2* part = reinterpret_cast<float2*>(smem + SM_PART);   // [8][64]
    float* red = reinterpret_cast<float*>(smem + SM_RED);

    // stage K-window hi/lo [r=0..127][chunk=0..15], chunk = 8 h-values (16B bf16)
    for (int idx = tid; idx < TW*16; idx += 256) {
        int r = idx >> 4, ch = idx & 15;
        int tg = t0 + r;
        float v[8];
        if (tg >= 0 && tg < SS) {
            const float4* p = reinterpret_cast<const float4*>(
                &g_kn[((size_t)j*SS + tg)*HH + ch*8]);
            float4 a = p[0], b = p[1];
            v[0]=a.x; v[1]=a.y; v[2]=a.z; v[3]=a.w; v[4]=b.x; v[5]=b.y; v[6]=b.z; v[7]=b.w;
        } else {
            #pragma unroll
            for (int x = 0; x < 8; x++) v[x] = 0.f;
        }
        uint4 hi, lo; split8(v, hi, lo);
        uint32_t off = (uint32_t)(r*256 + ((ch ^ (r & 7)) << 4));
        *reinterpret_cast<uint4*>(smem + SM_A_HI + off) = hi;
        *reinterpret_cast<uint4*>(smem + SM_A_LO + off) = lo;
    }
    if (tid < TW) { int tg = t0 + tid; kmw[tid] = (tg >= 0 && tg < SS) ? km[j*SS + tg] : 0.f; }
    if (tid >= 128 && tid <= 128+TT) wt[tid-128] = g_wtab[tid-128];
    __syncthreads();

    float kc_j = g_kcnt[j];
    int g_ = lane >> 2, t_ = lane & 3;

    for (int ii = 0; ii < IGROUP; ii++) {
        int i = ig*IGROUP + ii;

        // stage Q tile hi/lo [r=0..63][chunk]
        for (int idx = tid; idx < SC*16; idx += 256) {
            int r = idx >> 4, ch = idx & 15;
            const float4* p = reinterpret_cast<const float4*>(
                &g_qn[((size_t)i*SS + s0 + r)*HH + ch*8]);
            float4 a = p[0], b = p[1];
            float v[8] = {a.x,a.y,a.z,a.w,b.x,b.y,b.z,b.w};
            uint4 hi, lo; split8(v, hi, lo);
            uint32_t off = (uint32_t)(r*256 + ((ch ^ (r & 7)) << 4));
            *reinterpret_cast<uint4*>(smem + SM_B_HI + off) = hi;
            *reinterpret_cast<uint4*>(smem + SM_B_LO + off) = lo;
        }
        __syncthreads();

        // ---- GEMM ----
        float acc[8][4];
        #pragma unroll
        for (int nt = 0; nt < 8; nt++)
            #pragma unroll
            for (int x = 0; x < 4; x++) acc[nt][x] = 0.f;

        // A lane addressing: lanes 0-15 -> rows 0-15 chunk cb; 16-31 -> rows 0-15 chunk cb+1
        int a_row = wid*16 + (lane & 15);
        int a_sel = lane >> 4;
        uint32_t a_rowoff = (uint32_t)(a_row * 256);
        // B lane addressing: n_off = ((l>>4)<<3)+(l&7), chunk sel = (l>>3)&1
        int b_noff = ((lane >> 4) << 3) + (lane & 7);
        int b_sel = (lane >> 3) & 1;

        #pragma unroll
        for (int ks = 0; ks < 8; ks++) {
            int cb = 2*ks;
            uint32_t a_off = a_rowoff + (uint32_t)((((cb + a_sel) ^ (lane & 7)) << 4));
            uint32_t ah0,ah1,ah2,ah3, al0,al1,al2,al3;
            LDSM4(ah0,ah1,ah2,ah3, sb + SM_A_HI + a_off);
            LDSM4(al0,al1,al2,al3, sb + SM_A_LO + a_off);
            uint32_t b_chunk = (uint32_t)((((cb + b_sel) ^ (lane & 7)) << 4));
            #pragma unroll
            for (int np = 0; np < 4; np++) {
                uint32_t b_off = (uint32_t)((np*16 + b_noff) * 256) + b_chunk;
                uint32_t bh0,bh1,bh2,bh3, bl0,bl1,bl2,bl3;
                LDSM4(bh0,bh1,bh2,bh3, sb + SM_B_HI + b_off);
                LDSM4(bl0,bl1,bl2,bl3, sb + SM_B_LO + b_off);
                MMA16816(acc[2*np],   ah0,ah1,ah2,ah3, bh0,bh1);
                MMA16816(acc[2*np+1], ah0,ah1,ah2,ah3, bh2,bh3);
                MMA16816(acc[2*np],   ah0,ah1,ah2,ah3, bl0,bl1);
                MMA16816(acc[2*np+1], ah0,ah1,ah2,ah3, bl2,bl3);
                MMA16816(acc[2*np],   al0,al1,al2,al3, bh0,bh1);
                MMA16816(acc[2*np+1], al0,al1,al2,al3, bh2,bh3);
            }
        }

        // ---- epilogue ----
        // thread holds D rows r0=w*16+g, r1=r0+8; cols nt*8+2t, +1
        int r0 = wid*16 + g_;
        int r1 = r0 + 8;
        bool kok0 = kmw[r0] > 0.999f;
        bool kok1 = kmw[r1] > 0.999f;
        #pragma unroll
        for (int nt = 0; nt < 8; nt++) {
            int col0 = nt*8 + 2*t_;
            float gs0 = 0.f, gds0 = 0.f, gs1 = 0.f, gds1 = 0.f;
            {
                float d = acc[nt][0];
                int ad = r0 - col0 - TT; ad = (ad < 0) ? -ad : ad;
                if (ad <= TT && kok0) { float e = __expf(d * wt[ad]) - 1.0f; gs0 += e; gds0 += e*d; }
            }
            {
                float d = acc[nt][1];
                int ad = r0 - col0 - 1 - TT; ad = (ad < 0) ? -ad : ad;
                if (ad <= TT && kok0) { float e = __expf(d * wt[ad]) - 1.0f; gs1 += e; gds1 += e*d; }
            }
            {
                float d = acc[nt][2];
                int ad = r1 - col0 - TT; ad = (ad < 0) ? -ad : ad;
                if (ad <= TT && kok1) { float e = __expf(d * wt[ad]) - 1.0f; gs0 += e; gds0 += e*d; }
            }
            {
                float d = acc[nt][3];
                int ad = r1 - col0 - 1 - TT; ad = (ad < 0) ? -ad : ad;
                if (ad <= TT && kok1) { float e = __expf(d * wt[ad]) - 1.0f; gs1 += e; gds1 += e*d; }
            }
            // reduce over the 8 lane-groups (g); t stays fixed
            #pragma unroll
            for (int off = 4; off <= 16; off <<= 1) {
                gs0  += __shfl_xor_sync(0xffffffffu, gs0,  off);
                gds0 += __shfl_xor_sync(0xffffffffu, gds0, off);
                gs1  += __shfl_xor_sync(0xffffffffu, gs1,  off);
                gds1 += __shfl_xor_sync(0xffffffffu, gds1, off);
            }
            if (g_ == 0) {
                part[wid*64 + col0]     = make_float2(gs0, gds0);
                part[wid*64 + col0 + 1] = make_float2(gs1, gds1);
            }
        }
        __syncthreads();

        // final: threads 0-63 own s; sum all 8 warps
        if (tid < 64) {
            int s = tid;
            float G = 0.f, Gd = 0.f;
            #pragma unroll
            for (int w = 0; w < 8; w++) {
                float2 p2 = part[w*64 + s];
                G += p2.x; Gd += p2.y;
            }
            float S1v = g_S1[((size_t)i*BB + j)*SS + (s0 + s)];
            float qmv = qm[i*SS + s0 + s];
            float Z  = kc_j + G;
            float Nm = S1v + Gd;
            float local = qmv * ((Z > 1e-12f) ? (Nm / Z) : 0.f);
            #pragma unroll
            for (int off = 16; off >= 1; off >>= 1)
                local += __shfl_xor_sync(0xffffffffu, local, off);
            if ((tid & 31) == 0) red[tid >> 5] = local;
        }
        __syncthreads();
        if (tid == 0)
            g_partial[((size_t)i*BB + j)*NC + c] = red[0] + red[1];
        __syncthreads();   // part/red reuse + Q restage safe for next ii
    }
}

// ---------------- K5: final reduce ----------------
__global__ void k_final(float* __restrict__ out) {
    int tid = threadIdx.x;
    float s = 0.f;
    #pragma unroll
    for (int c = 0; c < NC; c++) s += g_partial[tid*NC + c];
    out[tid] = s / g_qdenom[tid >> 4];
}

// ---------------- launch ----------------
extern "C" void kernel_launch(void* const* d_in, const int* in_sizes, int n_in,
                              void* d_out, int out_size) {
    const float* qe = (const float*)d_in[0];
    const float* ke = (const float*)d_in[1];
    const float* qm = (const float*)d_in[2];
    const float* km = (const float*)d_in[3];
    float* out = (float*)d_out;

    cudaFuncSetAttribute(k_main, cudaFuncAttributeMaxDynamicSharedMemorySize, SMEM_TOTAL);

    k_norm <<<(2*BB*SS)/8, 256>>>(qe, ke);
    k_prep <<<BB*4, 128>>>(km, qm);
    k_s1   <<<(BB*SS)/8, 256>>>();
    k_main <<<dim3(NC, BB, BB/IGROUP), 256, SMEM_TOTAL>>>(qm, km);
    k_final<<<1, 256>>>(out);
}

// round 7
// speedup vs baseline: 3.2223x; 1.1861x over previous
#include <cuda_runtime.h>
#include <cuda_bf16.h>
#include <math.h>
#include <cstdint>

// Problem constants
#define BB 16
#define SS 512
#define HH 128
#define TT 32
#define SC 64      // s-chunk (N of GEMM)
#define TW 128     // t-window (M of GEMM)
#define NC (SS/SC)
#define IGROUP 4   // i's per block

// smem byte offsets: K/Q tiles bf16 K-major, rows of 256B (16 chunks of 16B, XOR-swizzled)
#define SM_A    0           // K-window [128][128] bf16 = 32768
#define SM_B    32768       // Q tile   [64][128] bf16 = 16384
#define SM_KMW  49152       // 128 floats
#define SM_WT   49664       // 33 floats (pad to 160B)
#define SM_PART 49824       // [8][64] float2 = 4096
#define SM_RED  53920       // 2 floats
#define SMEM_TOTAL 53952

// ---------------- device scratch ----------------
__device__ float g_qn[BB*SS*HH];
__device__ float g_kn[BB*SS*HH];
__device__ float g_ksum4[BB*4*HH];
__device__ float g_cnt4[BB*4*2];
__device__ float g_kcnt[BB];
__device__ float g_qdenom[BB];
__device__ float g_S1[BB*BB*SS];
__device__ float g_partial[BB*BB*NC];
__device__ float g_wtab[TT+1];

// ---------------- helpers ----------------
__device__ __forceinline__ uint32_t smem_u32(const void* p) {
    uint32_t a;
    asm("{ .reg .u64 t; cvta.to.shared.u64 t, %1; cvt.u32.u64 %0, t; }" : "=r"(a) : "l"(p));
    return a;
}

#define LDSM4(r0,r1,r2,r3,addr) \
    asm volatile("ldmatrix.sync.aligned.m8n8.x4.shared.b16 {%0,%1,%2,%3}, [%4];" \
        : "=r"(r0), "=r"(r1), "=r"(r2), "=r"(r3) : "r"(addr))

#define MMA16816(d, a0,a1,a2,a3, b0,b1) \
    asm volatile("mma.sync.aligned.m16n8k16.row.col.f32.bf16.bf16.f32 " \
        "{%0,%1,%2,%3}, {%4,%5,%6,%7}, {%8,%9}, {%0,%1,%2,%3};" \
        : "+f"((d)[0]), "+f"((d)[1]), "+f"((d)[2]), "+f"((d)[3]) \
        : "r"(a0), "r"(a1), "r"(a2), "r"(a3), "r"(b0), "r"(b1))

// pack 8 floats -> uint4 of bf16x2 (rn)
__device__ __forceinline__ uint4 pack8(const float* v) {
    uint32_t h[4];
    #pragma unroll
    for (int p = 0; p < 4; p++) {
        __nv_bfloat162 hp = __floats2bfloat162_rn(v[2*p], v[2*p+1]);
        h[p] = *reinterpret_cast<uint32_t*>(&hp);
    }
    return make_uint4(h[0], h[1], h[2], h[3]);
}

// ---------------- K1: L2-normalize ----------------
__global__ void k_norm(const float* __restrict__ qe, const float* __restrict__ ke) {
    int row  = blockIdx.x * 8 + (threadIdx.x >> 5);
    int lane = threadIdx.x & 31;
    const float* src; float* dst;
    if (row < BB*SS) { src = qe + (size_t)row*HH; dst = g_qn + (size_t)row*HH; }
    else             { int r = row - BB*SS; src = ke + (size_t)r*HH; dst = g_kn + (size_t)r*HH; }
    float4 v = reinterpret_cast<const float4*>(src)[lane];
    float ss = v.x*v.x + v.y*v.y + v.z*v.z + v.w*v.w;
    #pragma unroll
    for (int off = 16; off >= 1; off >>= 1) ss += __shfl_xor_sync(0xffffffffu, ss, off);
    float sc = 1.0f / fmaxf(sqrtf(ss), 1e-12f);
    v.x *= sc; v.y *= sc; v.z *= sc; v.w *= sc;
    reinterpret_cast<float4*>(dst)[lane] = v;
}

// ---------------- K2: per-(j, quarter) masked key sums + counts ----------------
__global__ void k_prep(const float* __restrict__ km, const float* __restrict__ qm) {
    __shared__ float kms[128];
    __shared__ float reda[4], redb[4];
    int b = blockIdx.x;
    int j = b >> 2, q = b & 3;
    int tid = threadIdx.x;
    int tbase = q * 128;
    float kmv = (km[j*SS + tbase + tid] > 0.999f) ? 1.0f : 0.0f;
    float qmv = qm[j*SS + tbase + tid];
    kms[tid] = kmv;
    __syncthreads();
    float acc = 0.0f;
    #pragma unroll 4
    for (int t = 0; t < 128; t++)
        acc += g_kn[((size_t)j*SS + tbase + t)*HH + tid] * kms[t];
    g_ksum4[(size_t)b*HH + tid] = acc;
    float a = kmv, b2 = qmv;
    #pragma unroll
    for (int off = 16; off >= 1; off >>= 1) {
        a  += __shfl_xor_sync(0xffffffffu, a, off);
        b2 += __shfl_xor_sync(0xffffffffu, b2, off);
    }
    if ((tid & 31) == 0) { reda[tid >> 5] = a; redb[tid >> 5] = b2; }
    __syncthreads();
    if (tid == 0) {
        g_cnt4[b*2 + 0] = reda[0]+reda[1]+reda[2]+reda[3];
        g_cnt4[b*2 + 1] = redb[0]+redb[1]+redb[2]+redb[3];
    }
    if (b == 0 && tid <= TT) g_wtab[tid] = expf(-0.5f * (float)tid);
}

// ---------------- K3: S1 + finalize counts ----------------
__global__ void k_s1() {
    __shared__ float ks[BB*HH];
    int tid = threadIdx.x;
    for (int x = tid; x < BB*HH; x += 256) {
        int jj = x >> 7, hh = x & (HH-1);
        float v = 0.f;
        #pragma unroll
        for (int p = 0; p < 4; p++) v += g_ksum4[((size_t)jj*4 + p)*HH + hh];
        ks[x] = v;
    }
    if (blockIdx.x == 0 && tid < BB) {
        float a = 0.f, b = 0.f;
        #pragma unroll
        for (int p = 0; p < 4; p++) { a += g_cnt4[(tid*4+p)*2+0]; b += g_cnt4[(tid*4+p)*2+1]; }
        g_kcnt[tid]   = a;
        g_qdenom[tid] = fmaxf(b, 1.0f);
    }
    __syncthreads();
    int w = tid >> 5, lane = tid & 31;
    int row = blockIdx.x * 8 + w;
    int i = row >> 9, s = row & (SS-1);
    float4 q = *reinterpret_cast<const float4*>(&g_qn[(size_t)row*HH + lane*4]);
    #pragma unroll
    for (int j = 0; j < BB; j++) {
        float4 k4 = *reinterpret_cast<const float4*>(&ks[j*HH + lane*4]);
        float p = q.x*k4.x + q.y*k4.y + q.z*k4.z + q.w*k4.w;
        #pragma unroll
        for (int off = 16; off >= 1; off >>= 1) p += __shfl_xor_sync(0xffffffffu, p, off);
        if (lane == 0) g_S1[((size_t)i*BB + j)*SS + s] = p;
    }
}

// ---------------- K4: main banded kernel — mma.sync bf16 GEMM (single pass) ----------------
// block = (c, j, ig); loops 4 i's. D[t=128][s=64] = K_win * Q^T.
// warp w owns t rows w*16..w*16+15 (full 64 s cols), m16n8k16 fragments.
__global__ __launch_bounds__(256) void k_main(const float* __restrict__ qm,
                                              const float* __restrict__ km) {
    extern __shared__ char smem[];
    uint32_t sb = smem_u32(smem);
    int c = blockIdx.x, j = blockIdx.y, ig = blockIdx.z;
    int tid = threadIdx.x;
    int wid = tid >> 5, lane = tid & 31;
    int t0 = c*SC - TT;
    int s0 = c*SC;

    float* kmw = reinterpret_cast<float*>(smem + SM_KMW);
    float* wt  = reinterpret_cast<float*>(smem + SM_WT);
    float2* part = reinterpret_cast<float2*>(smem + SM_PART);   // [8][64]
    float* red = reinterpret_cast<float*>(smem + SM_RED);

    // stage K-window [r=0..127][chunk=0..15], chunk = 8 h-values (16B bf16)
    for (int idx = tid; idx < TW*16; idx += 256) {
        int r = idx >> 4, ch = idx & 15;
        int tg = t0 + r;
        float v[8];
        if (tg >= 0 && tg < SS) {
            const float4* p = reinterpret_cast<const float4*>(
                &g_kn[((size_t)j*SS + tg)*HH + ch*8]);
            float4 a = p[0], b = p[1];
            v[0]=a.x; v[1]=a.y; v[2]=a.z; v[3]=a.w; v[4]=b.x; v[5]=b.y; v[6]=b.z; v[7]=b.w;
        } else {
            #pragma unroll
            for (int x = 0; x < 8; x++) v[x] = 0.f;
        }
        uint32_t off = (uint32_t)(r*256 + ((ch ^ (r & 7)) << 4));
        *reinterpret_cast<uint4*>(smem + SM_A + off) = pack8(v);
    }
    if (tid < TW) { int tg = t0 + tid; kmw[tid] = (tg >= 0 && tg < SS) ? km[j*SS + tg] : 0.f; }
    if (tid >= 128 && tid <= 128+TT) wt[tid-128] = g_wtab[tid-128];
    __syncthreads();

    float kc_j = g_kcnt[j];
    int g_ = lane >> 2, t_ = lane & 3;

    for (int ii = 0; ii < IGROUP; ii++) {
        int i = ig*IGROUP + ii;

        // stage Q tile [r=0..63][chunk]
        for (int idx = tid; idx < SC*16; idx += 256) {
            int r = idx >> 4, ch = idx & 15;
            const float4* p = reinterpret_cast<const float4*>(
                &g_qn[((size_t)i*SS + s0 + r)*HH + ch*8]);
            float4 a = p[0], b = p[1];
            float v[8] = {a.x,a.y,a.z,a.w,b.x,b.y,b.z,b.w};
            uint32_t off = (uint32_t)(r*256 + ((ch ^ (r & 7)) << 4));
            *reinterpret_cast<uint4*>(smem + SM_B + off) = pack8(v);
        }
        __syncthreads();

        // ---- GEMM ----
        float acc[8][4];
        #pragma unroll
        for (int nt = 0; nt < 8; nt++)
            #pragma unroll
            for (int x = 0; x < 4; x++) acc[nt][x] = 0.f;

        // A lane addressing: lanes 0-15 -> rows 0-15 chunk cb; 16-31 -> rows 0-15 chunk cb+1
        int a_row = wid*16 + (lane & 15);
        int a_sel = lane >> 4;
        uint32_t a_rowoff = (uint32_t)(a_row * 256);
        // B lane addressing: n_off = ((l>>4)<<3)+(l&7), chunk sel = (l>>3)&1
        int b_noff = ((lane >> 4) << 3) + (lane & 7);
        int b_sel = (lane >> 3) & 1;

        #pragma unroll
        for (int ks = 0; ks < 8; ks++) {
            int cb = 2*ks;
            uint32_t a_off = a_rowoff + (uint32_t)((((cb + a_sel) ^ (lane & 7)) << 4));
            uint32_t ah0,ah1,ah2,ah3;
            LDSM4(ah0,ah1,ah2,ah3, sb + SM_A + a_off);
            uint32_t b_chunk = (uint32_t)((((cb + b_sel) ^ (lane & 7)) << 4));
            #pragma unroll
            for (int np = 0; np < 4; np++) {
                uint32_t b_off = (uint32_t)((np*16 + b_noff) * 256) + b_chunk;
                uint32_t bh0,bh1,bh2,bh3;
                LDSM4(bh0,bh1,bh2,bh3, sb + SM_B + b_off);
                MMA16816(acc[2*np],   ah0,ah1,ah2,ah3, bh0,bh1);
                MMA16816(acc[2*np+1], ah0,ah1,ah2,ah3, bh2,bh3);
            }
        }

        // ---- epilogue ----
        // thread holds D rows r0=w*16+g, r1=r0+8; cols nt*8+2t, +1
        int r0 = wid*16 + g_;
        int r1 = r0 + 8;
        bool kok0 = kmw[r0] > 0.999f;
        bool kok1 = kmw[r1] > 0.999f;
        #pragma unroll
        for (int nt = 0; nt < 8; nt++) {
            int col0 = nt*8 + 2*t_;
            float gs0 = 0.f, gds0 = 0.f, gs1 = 0.f, gds1 = 0.f;
            {
                float d = acc[nt][0];
                int ad = r0 - col0 - TT; ad = (ad < 0) ? -ad : ad;
                if (ad <= TT && kok0) { float e = __expf(d * wt[ad]) - 1.0f; gs0 += e; gds0 += e*d; }
            }
            {
                float d = acc[nt][1];
                int ad = r0 - col0 - 1 - TT; ad = (ad < 0) ? -ad : ad;
                if (ad <= TT && kok0) { float e = __expf(d * wt[ad]) - 1.0f; gs1 += e; gds1 += e*d; }
            }
            {
                float d = acc[nt][2];
                int ad = r1 - col0 - TT; ad = (ad < 0) ? -ad : ad;
                if (ad <= TT && kok1) { float e = __expf(d * wt[ad]) - 1.0f; gs0 += e; gds0 += e*d; }
            }
            {
                float d = acc[nt][3];
                int ad = r1 - col0 - 1 - TT; ad = (ad < 0) ? -ad : ad;
                if (ad <= TT && kok1) { float e = __expf(d * wt[ad]) - 1.0f; gs1 += e; gds1 += e*d; }
            }
            // reduce over the 8 lane-groups (g); t stays fixed
            #pragma unroll
            for (int off = 4; off <= 16; off <<= 1) {
                gs0  += __shfl_xor_sync(0xffffffffu, gs0,  off);
                gds0 += __shfl_xor_sync(0xffffffffu, gds0, off);
                gs1  += __shfl_xor_sync(0xffffffffu, gs1,  off);
                gds1 += __shfl_xor_sync(0xffffffffu, gds1, off);
            }
            if (g_ == 0) {
                part[wid*64 + col0]     = make_float2(gs0, gds0);
                part[wid*64 + col0 + 1] = make_float2(gs1, gds1);
            }
        }
        __syncthreads();

        // final: threads 0-63 own s; sum all 8 warps
        if (tid < 64) {
            int s = tid;
            float G = 0.f, Gd = 0.f;
            #pragma unroll
            for (int w = 0; w < 8; w++) {
                float2 p2 = part[w*64 + s];
                G += p2.x; Gd += p2.y;
            }
            float S1v = g_S1[((size_t)i*BB + j)*SS + (s0 + s)];
            float qmv = qm[i*SS + s0 + s];
            float Z  = kc_j + G;
            float Nm = S1v + Gd;
            float local = qmv * ((Z > 1e-12f) ? (Nm / Z) : 0.f);
            #pragma unroll
            for (int off = 16; off >= 1; off >>= 1)
                local += __shfl_xor_sync(0xffffffffu, local, off);
            if ((tid & 31) == 0) red[tid >> 5] = local;
        }
        __syncthreads();
        if (tid == 0)
            g_partial[((size_t)i*BB + j)*NC + c] = red[0] + red[1];
        __syncthreads();   // part/red reuse + Q restage safe for next ii
    }
}

// ---------------- K5: final reduce ----------------
__global__ void k_final(float* __restrict__ out) {
    int tid = threadIdx.x;
    float s = 0.f;
    #pragma unroll
    for (int c = 0; c < NC; c++) s += g_partial[tid*NC + c];
    out[tid] = s / g_qdenom[tid >> 4];
}

// ---------------- launch ----------------
extern "C" void kernel_launch(void* const* d_in, const int* in_sizes, int n_in,
                              void* d_out, int out_size) {
    const float* qe = (const float*)d_in[0];
    const float* ke = (const float*)d_in[1];
    const float* qm = (const float*)d_in[2];
    const float* km = (const float*)d_in[3];
    float* out = (float*)d_out;

    cudaFuncSetAttribute(k_main, cudaFuncAttributeMaxDynamicSharedMemorySize, SMEM_TOTAL);

    k_norm <<<(2*BB*SS)/8, 256>>>(qe, ke);
    k_prep <<<BB*4, 128>>>(km, qm);
    k_s1   <<<(BB*SS)/8, 256>>>();
    k_main <<<dim3(NC, BB, BB/IGROUP), 256, SMEM_TOTAL>>>(qm, km);
    k_final<<<1, 256>>>(out);
}